// round 1
// baseline (speedup 1.0000x reference)
#include <cuda_runtime.h>
#include <math.h>

// Problem constants
#define Bn 4
#define Nn 4096
#define Kn 16
#define DP 64
#define DM 128
#define NODES (Bn*Nn)            // 16384
#define ATT_OFF (NODES*DP)       // 1048576 : out region first, attn after
#define SCALE_F 0.08838834764831845f

// Scratch (device globals -- no allocation allowed)
__device__ int   g_idx[NODES*Kn];
__device__ float g_x [NODES*DM];
__device__ float g_q [NODES*DM];
__device__ float g_k [NODES*DM];
__device__ float g_v [NODES*DM];

// ---------------------------------------------------------------------------
// Kernel 1: KNN.  grid (16, 4) x 256 threads. One thread per query point.
// Maintains ascending (d, idx) top-16, matching jax.lax.top_k(-d2, K)
// (ties -> lower index first; strict '<' with ascending j gives that).
// ---------------------------------------------------------------------------
__global__ void __launch_bounds__(256) knn_kernel(const float* __restrict__ xyz) {
    __shared__ float sx[Nn];
    __shared__ float sy[Nn];
    __shared__ float sz[Nn];
    int b = blockIdx.y;
    const float* base = xyz + (size_t)b * Nn * 3;
    for (int i = threadIdx.x; i < Nn; i += 256) {
        sx[i] = base[i*3+0];
        sy[i] = base[i*3+1];
        sz[i] = base[i*3+2];
    }
    __syncthreads();

    int q = blockIdx.x * 256 + threadIdx.x;
    float qx = sx[q], qy = sy[q], qz = sz[q];

    float bd[Kn];
    int   bi[Kn];
#pragma unroll
    for (int m = 0; m < Kn; m++) { bd[m] = 3.4e38f; bi[m] = 0x7fffffff; }
    float worst = 3.4e38f;

    for (int j = 0; j < Nn; j++) {
        float dx = qx - sx[j];
        float dy = qy - sy[j];
        float dz = qz - sz[j];
        // left-to-right, non-fused sum to track reference rounding
        float d = __fadd_rn(__fadd_rn(__fmul_rn(dx,dx), __fmul_rn(dy,dy)),
                            __fmul_rn(dz,dz));
        if (d < worst) {
            int p = Kn - 1;
            while (p > 0 && d < bd[p-1]) {
                bd[p] = bd[p-1]; bi[p] = bi[p-1]; p--;
            }
            bd[p] = d; bi[p] = j;
            worst = bd[Kn-1];
        }
    }
    int* op = g_idx + ((size_t)(b*Nn + q)) * Kn;
#pragma unroll
    for (int m = 0; m < Kn; m++) op[m] = bi[m];
}

// ---------------------------------------------------------------------------
// Kernel 2a: x = features @ fc1_w + fc1_b   (16384x64 @ 64x128)
// block = 256 threads = 8 warps = 8 rows; grid 2048.
// ---------------------------------------------------------------------------
__global__ void __launch_bounds__(256) proj_x_kernel(const float* __restrict__ features,
                                                     const float* __restrict__ fc1_w,
                                                     const float* __restrict__ fc1_b) {
    __shared__ float sW1[64*128];
    __shared__ float sRow[8*64];
    int t = threadIdx.x;
    int row0 = blockIdx.x * 8;
    for (int o = t; o < 64*128; o += 256) sW1[o] = fc1_w[o];
    for (int o = t; o < 8*64;   o += 256) sRow[o] = features[(size_t)row0*64 + o];
    __syncthreads();

    int w = t >> 5, lane = t & 31;
    float acc[4];
#pragma unroll
    for (int j = 0; j < 4; j++) acc[j] = fc1_b[lane + j*32];
#pragma unroll 8
    for (int k = 0; k < 64; k++) {
        float f = sRow[w*64 + k];
#pragma unroll
        for (int j = 0; j < 4; j++)
            acc[j] = fmaf(f, sW1[k*128 + lane + j*32], acc[j]);
    }
#pragma unroll
    for (int j = 0; j < 4; j++)
        g_x[(size_t)(row0 + w)*128 + lane + j*32] = acc[j];
}

// ---------------------------------------------------------------------------
// Kernel 2b: q/k/v = x @ {wq,wk,wv}  (16384x128 @ 128x128, x3)
// block = 256 threads = 8 rows; weights all staged in smem (192KB).
// ---------------------------------------------------------------------------
__global__ void __launch_bounds__(256) proj_qkv_kernel(const float* __restrict__ wq,
                                                       const float* __restrict__ wk,
                                                       const float* __restrict__ wv) {
    extern __shared__ float sm2[];
    float* sW   = sm2;               // 3 * 16384
    float* sRow = sm2 + 3*16384;     // 1024
    int t = threadIdx.x;
    int row0 = blockIdx.x * 8;
    for (int o = t; o < 16384; o += 256) {
        sW[o]         = wq[o];
        sW[16384 + o] = wk[o];
        sW[32768 + o] = wv[o];
    }
    for (int o = t; o < 1024; o += 256) sRow[o] = g_x[(size_t)row0*128 + o];
    __syncthreads();

    int w = t >> 5, lane = t & 31;
    float* outs[3] = {g_q, g_k, g_v};
#pragma unroll
    for (int m = 0; m < 3; m++) {
        float acc[4] = {0.f, 0.f, 0.f, 0.f};
        const float* Wm = sW + m*16384;
#pragma unroll 4
        for (int k = 0; k < 128; k++) {
            float f = sRow[w*128 + k];
#pragma unroll
            for (int j = 0; j < 4; j++)
                acc[j] = fmaf(f, Wm[k*128 + lane + j*32], acc[j]);
        }
#pragma unroll
        for (int j = 0; j < 4; j++)
            outs[m][(size_t)(row0 + w)*128 + lane + j*32] = acc[j];
    }
}

// ---------------------------------------------------------------------------
// smem GEMM: C[64x128] = A[64x128] @ W[128x128] (+bias, optional relu)
// A, C padded to stride 132. 256 threads, 4x8 register tile each.
// ---------------------------------------------------------------------------
__device__ __forceinline__ void gemm_64x128(const float* __restrict__ sA,
                                            const float* __restrict__ sW,
                                            float* __restrict__ sC,
                                            const float* __restrict__ bias,
                                            bool do_relu, int t) {
    int tx = t & 15;
    int r0 = (t >> 4) * 4;
    float acc[4][8];
#pragma unroll
    for (int j = 0; j < 8; j++) {
        float bv = bias[tx + j*16];
#pragma unroll
        for (int i = 0; i < 4; i++) acc[i][j] = bv;
    }
#pragma unroll 4
    for (int kk = 0; kk < 128; kk++) {
        float a[4], w[8];
#pragma unroll
        for (int i = 0; i < 4; i++) a[i] = sA[(r0+i)*132 + kk];
#pragma unroll
        for (int j = 0; j < 8; j++) w[j] = sW[kk*128 + tx + j*16];
#pragma unroll
        for (int i = 0; i < 4; i++)
#pragma unroll
            for (int j = 0; j < 8; j++)
                acc[i][j] = fmaf(a[i], w[j], acc[i][j]);
    }
#pragma unroll
    for (int i = 0; i < 4; i++)
#pragma unroll
        for (int j = 0; j < 8; j++) {
            float v = acc[i][j];
            if (do_relu) v = fmaxf(v, 0.f);
            sC[(r0+i)*132 + tx + j*16] = v;
        }
}

// ---------------------------------------------------------------------------
// Kernel 3: fused main. 4 nodes (64 K-rows) per CTA, 256 threads, 4096 CTAs.
// pos_enc -> h -> gamma MLP -> softmax(K) -> attn out -> res -> out.
// ---------------------------------------------------------------------------
__global__ void __launch_bounds__(256, 1) main_kernel(
    const float* __restrict__ xyz, const float* __restrict__ features,
    const float* __restrict__ d1_w, const float* __restrict__ d1_b,
    const float* __restrict__ d2_w, const float* __restrict__ d2_b,
    const float* __restrict__ g1_w, const float* __restrict__ g1_b,
    const float* __restrict__ g2_w, const float* __restrict__ g2_b,
    const float* __restrict__ fc2_w, const float* __restrict__ fc2_b,
    float* __restrict__ out)
{
    extern __shared__ float sm[];
    float* sW   = sm;                 // 16384
    float* sA   = sW   + 16384;       // 64*132 = 8448
    float* sC   = sA   + 8448;        // 8448
    float* sPos = sC   + 8448;        // 8448
    float* sQ   = sPos + 8448;        // 512
    float* sRes = sQ   + 512;         // 512
    float* sD1  = sRes + 512;         // 384
    float* sD1b = sD1  + 384;         // 128
    float* sD2b = sD1b + 128;         // 128
    float* sG1b = sD2b + 128;         // 128
    float* sG2b = sG1b + 128;         // 128
    float* sRel = sG2b + 128;         // 192
    int*   sIdx = (int*)(sRel + 192); // 64

    int t = threadIdx.x;
    int g0 = blockIdx.x * 4;          // first global node of this CTA
    int bbase = (g0 >> 12) << 12;     // b * 4096

    // Phase 0: small loads
    if (t < 64) sIdx[t] = g_idx[(size_t)g0*Kn + t];
    for (int o = t; o < 512; o += 256) sQ[o] = g_q[(size_t)g0*128 + o];
    for (int o = t; o < 384; o += 256) sD1[o] = d1_w[o];
    if (t < 128) {
        sD1b[t] = d1_b[t]; sD2b[t] = d2_b[t];
        sG1b[t] = g1_b[t]; sG2b[t] = g2_b[t];
    }
    __syncthreads();

    // Phase 1: rel = xyz[query] - xyz[neighbor]
    if (t < 64) {
        int nn = t >> 4;
        int n  = g0 + nn;
        int j  = sIdx[t];
        const float* pq = xyz + (size_t)n * 3;
        const float* pj = xyz + (size_t)(bbase + j) * 3;
        sRel[t*3+0] = pq[0] - pj[0];
        sRel[t*3+1] = pq[1] - pj[1];
        sRel[t*3+2] = pq[2] - pj[2];
    }
    __syncthreads();

    // Phase 2: t1 = relu(rel @ d1 + d1_b) -> sA ; load d2 -> sW
    for (int o = t; o < 8192; o += 256) {
        int r = o >> 7, c = o & 127;
        float v = sD1b[c];
        v = fmaf(sRel[r*3+0], sD1[c],       v);
        v = fmaf(sRel[r*3+1], sD1[128 + c], v);
        v = fmaf(sRel[r*3+2], sD1[256 + c], v);
        sA[r*132 + c] = fmaxf(v, 0.f);
    }
    for (int o = t; o < 16384; o += 256) sW[o] = d2_w[o];
    __syncthreads();

    // Phase 3: pos = t1 @ d2 + d2_b
    gemm_64x128(sA, sW, sPos, sD2b, false, t);
    __syncthreads();

    // Phase 4: h = q - k_gather + pos -> sA ; load g1 -> sW
    for (int o = t; o < 8192; o += 256) {
        int r = o >> 7, c = o & 127;
        int nn = r >> 4;
        int j = sIdx[r];
        float kv = g_k[(size_t)(bbase + j)*128 + c];
        sA[r*132 + c] = sQ[nn*128 + c] - kv + sPos[r*132 + c];
    }
    for (int o = t; o < 16384; o += 256) sW[o] = g1_w[o];
    __syncthreads();

    // Phase 5: a1 = relu(h @ g1 + g1_b)
    gemm_64x128(sA, sW, sC, sG1b, true, t);
    __syncthreads();

    // Phase 6: load g2
    for (int o = t; o < 16384; o += 256) sW[o] = g2_w[o];
    __syncthreads();

    // Phase 7: logits = a1 @ g2 + g2_b -> sA
    gemm_64x128(sC, sW, sA, sG2b, false, t);
    __syncthreads();

    // Phase 8: softmax over K (per node, per channel); res accumulation
    for (int p = t; p < 512; p += 256) {
        int nn = p >> 7, c = p & 127;
        int r0 = nn << 4;
        float m = -3.4e38f;
#pragma unroll
        for (int k = 0; k < Kn; k++) m = fmaxf(m, sA[(r0+k)*132 + c]);
        float e[Kn];
        float ssum = 0.f;
#pragma unroll
        for (int k = 0; k < Kn; k++) {
            e[k] = __expf((sA[(r0+k)*132 + c] - m) * SCALE_F);
            ssum += e[k];
        }
        float inv = 1.f / ssum;
        float racc = 0.f;
#pragma unroll
        for (int k = 0; k < Kn; k++) {
            float a = e[k] * inv;
            sC[(r0+k)*132 + c] = a;
            int j = sIdx[r0 + k];
            float vp = g_v[(size_t)(bbase + j)*128 + c] + sPos[(r0+k)*132 + c];
            racc = fmaf(a, vp, racc);
        }
        sRes[nn*128 + c] = racc;
    }
    __syncthreads();

    // Phase 9a: dump attn (contiguous block for this CTA)
    {
        float* attn_base = out + (size_t)ATT_OFF + (size_t)g0 * (Kn * DM);
        for (int o = t; o < 8192; o += 256) {
            int r = o >> 7, c = o & 127;
            attn_base[o] = sC[r*132 + c];
        }
    }

    // Phase 9b: out = res @ fc2 + fc2_b + pre   (4 nodes x 64 = 256 outputs)
    {
        int nn = t >> 6, d = t & 63;
        float acc = fc2_b[d] + features[(size_t)(g0 + nn)*64 + d];
        const float* rr = sRes + nn*128;
#pragma unroll 8
        for (int c = 0; c < 128; c++)
            acc = fmaf(rr[c], fc2_w[c*64 + d], acc);
        out[(size_t)(g0 + nn)*64 + d] = acc;
    }
}

// ---------------------------------------------------------------------------
extern "C" void kernel_launch(void* const* d_in, const int* in_sizes, int n_in,
                              void* d_out, int out_size) {
    const float* xyz   = (const float*)d_in[0];
    const float* feats = (const float*)d_in[1];
    const float* fc1_w = (const float*)d_in[2];
    const float* fc1_b = (const float*)d_in[3];
    const float* fc2_w = (const float*)d_in[4];
    const float* fc2_b = (const float*)d_in[5];
    const float* d1_w  = (const float*)d_in[6];
    const float* d1_b  = (const float*)d_in[7];
    const float* d2_w  = (const float*)d_in[8];
    const float* d2_b  = (const float*)d_in[9];
    const float* g1_w  = (const float*)d_in[10];
    const float* g1_b  = (const float*)d_in[11];
    const float* g2_w  = (const float*)d_in[12];
    const float* g2_b  = (const float*)d_in[13];
    const float* wq    = (const float*)d_in[14];
    const float* wk    = (const float*)d_in[15];
    const float* wv    = (const float*)d_in[16];
    float* outp = (float*)d_out;

    const int SMEM_QKV  = (3*16384 + 1024) * 4;   // 200704 B
    const int SMEM_MAIN = 43904 * 4;              // 175616 B
    cudaFuncSetAttribute(proj_qkv_kernel, cudaFuncAttributeMaxDynamicSharedMemorySize, SMEM_QKV);
    cudaFuncSetAttribute(main_kernel,     cudaFuncAttributeMaxDynamicSharedMemorySize, SMEM_MAIN);

    knn_kernel<<<dim3(Nn/256, Bn), 256>>>(xyz);
    proj_x_kernel<<<NODES/8, 256>>>(feats, fc1_w, fc1_b);
    proj_qkv_kernel<<<NODES/8, 256, SMEM_QKV>>>(wq, wk, wv);
    main_kernel<<<NODES/4, 256, SMEM_MAIN>>>(xyz, feats,
                                             d1_w, d1_b, d2_w, d2_b,
                                             g1_w, g1_b, g2_w, g2_b,
                                             fc2_w, fc2_b, outp);
}

// round 2
// speedup vs baseline: 1.5083x; 1.5083x over previous
#include <cuda_runtime.h>
#include <math.h>

// Problem constants
#define Bn 4
#define Nn 4096
#define Kn 16
#define DP 64
#define DM 128
#define NODES (Bn*Nn)            // 16384
#define ATT_OFF (NODES*DP)       // out region first, attn after
#define SCALE_F 0.08838834764831845f

typedef unsigned long long ull;

// Scratch (device globals -- no allocation allowed)
__device__ int   g_idx[NODES*Kn];
__device__ float g_q [NODES*DM];
__device__ float g_k [NODES*DM];
__device__ float g_v [NODES*DM];

// ---------------------------------------------------------------------------
// f32x2 packed helpers (B300 FFMA2 path -- only reachable via PTX)
// ---------------------------------------------------------------------------
__device__ __forceinline__ ull pk2(float lo, float hi) {
    ull r;
    asm("mov.b64 %0, {%1,%2};" : "=l"(r)
        : "r"(__float_as_uint(lo)), "r"(__float_as_uint(hi)));
    return r;
}
__device__ __forceinline__ ull dup2f(float v) {
    ull r; unsigned u = __float_as_uint(v);
    asm("mov.b64 %0, {%1,%1};" : "=l"(r) : "r"(u));
    return r;
}
__device__ __forceinline__ void fma2(ull& d, ull a, ull b) {
    asm("fma.rn.f32x2 %0, %1, %2, %0;" : "+l"(d) : "l"(a), "l"(b));
}
__device__ __forceinline__ float2 up2(ull v) {
    unsigned lo, hi;
    asm("mov.b64 {%0,%1}, %2;" : "=r"(lo), "=r"(hi) : "l"(v));
    return make_float2(__uint_as_float(lo), __uint_as_float(hi));
}

// ---------------------------------------------------------------------------
// GEMM: out[64 x 128] = A[64 x KD](stride AS) @ W[KD x 128] (+bias, opt relu)
// 256 threads; each thread: 4 rows x 8 cols, packed f32x2 accumulators.
// A loads: float4 broadcast. W loads: 2x LDS.128 per k, conflict-free.
// out stride fixed 128 (smem or global).
// ---------------------------------------------------------------------------
template<int KD, int AS, bool RELU, bool HASB>
__device__ __forceinline__ void gemm64(const float* __restrict__ sA,
                                       const float* __restrict__ sW,
                                       float* __restrict__ outp,
                                       const float* __restrict__ bias,
                                       int t)
{
    const int tx = t & 15, c0 = tx * 8;
    const int r0 = (t >> 4) * 4;
    ull acc[4][4];
    if (HASB) {
#pragma unroll
        for (int j = 0; j < 4; j++) {
            ull b2 = pk2(bias[c0 + 2*j], bias[c0 + 2*j + 1]);
#pragma unroll
            for (int i = 0; i < 4; i++) acc[i][j] = b2;
        }
    } else {
#pragma unroll
        for (int i = 0; i < 4; i++)
#pragma unroll
            for (int j = 0; j < 4; j++) acc[i][j] = 0ULL;
    }

#pragma unroll 2
    for (int kk = 0; kk < KD; kk += 4) {
        float4 a4[4];
#pragma unroll
        for (int i = 0; i < 4; i++)
            a4[i] = *(const float4*)(sA + (r0 + i) * AS + kk);
#pragma unroll
        for (int kq = 0; kq < 4; kq++) {
            const float* wr = sW + (kk + kq) * 128 + c0;
            ulonglong2 wl = *(const ulonglong2*)(wr);
            ulonglong2 wh = *(const ulonglong2*)(wr + 4);
#pragma unroll
            for (int i = 0; i < 4; i++) {
                float av = (kq == 0) ? a4[i].x : (kq == 1) ? a4[i].y
                         : (kq == 2) ? a4[i].z : a4[i].w;
                ull ad = dup2f(av);
                fma2(acc[i][0], ad, wl.x);
                fma2(acc[i][1], ad, wl.y);
                fma2(acc[i][2], ad, wh.x);
                fma2(acc[i][3], ad, wh.y);
            }
        }
    }

#pragma unroll
    for (int i = 0; i < 4; i++) {
        float2 p0 = up2(acc[i][0]), p1 = up2(acc[i][1]);
        float2 p2 = up2(acc[i][2]), p3 = up2(acc[i][3]);
        float4 lo = make_float4(p0.x, p0.y, p1.x, p1.y);
        float4 hi = make_float4(p2.x, p2.y, p3.x, p3.y);
        if (RELU) {
            lo.x = fmaxf(lo.x, 0.f); lo.y = fmaxf(lo.y, 0.f);
            lo.z = fmaxf(lo.z, 0.f); lo.w = fmaxf(lo.w, 0.f);
            hi.x = fmaxf(hi.x, 0.f); hi.y = fmaxf(hi.y, 0.f);
            hi.z = fmaxf(hi.z, 0.f); hi.w = fmaxf(hi.w, 0.f);
        }
        *(float4*)(outp + (r0 + i) * 128 + c0)     = lo;
        *(float4*)(outp + (r0 + i) * 128 + c0 + 4) = hi;
    }
}

// ---------------------------------------------------------------------------
// Kernel 1: KNN. grid (32, 4) x 128 threads. One thread per query point.
// Ascending (d, idx) top-16 insertion; matches jax.lax.top_k(-d2, K) ties.
// ---------------------------------------------------------------------------
__global__ void __launch_bounds__(128) knn_kernel(const float* __restrict__ xyz) {
    __shared__ float sx[Nn];
    __shared__ float sy[Nn];
    __shared__ float sz[Nn];
    int b = blockIdx.y;
    const float* base = xyz + (size_t)b * Nn * 3;
    for (int i = threadIdx.x; i < Nn; i += 128) {
        sx[i] = base[i*3+0];
        sy[i] = base[i*3+1];
        sz[i] = base[i*3+2];
    }
    __syncthreads();

    int q = blockIdx.x * 128 + threadIdx.x;
    float qx = sx[q], qy = sy[q], qz = sz[q];

    float bd[Kn];
    int   bi[Kn];
#pragma unroll
    for (int m = 0; m < Kn; m++) { bd[m] = 3.4e38f; bi[m] = 0x7fffffff; }
    float worst = 3.4e38f;

    for (int j = 0; j < Nn; j += 4) {
        float d[4];
#pragma unroll
        for (int u = 0; u < 4; u++) {
            float dx = qx - sx[j+u];
            float dy = qy - sy[j+u];
            float dz = qz - sz[j+u];
            d[u] = __fadd_rn(__fadd_rn(__fmul_rn(dx,dx), __fmul_rn(dy,dy)),
                             __fmul_rn(dz,dz));
        }
#pragma unroll
        for (int u = 0; u < 4; u++) {
            if (d[u] < worst) {
                int p = Kn - 1;
                while (p > 0 && d[u] < bd[p-1]) {
                    bd[p] = bd[p-1]; bi[p] = bi[p-1]; p--;
                }
                bd[p] = d[u]; bi[p] = j + u;
                worst = bd[Kn-1];
            }
        }
    }
    int* op = g_idx + ((size_t)(b*Nn + q)) * Kn;
#pragma unroll
    for (int m = 0; m < Kn; m++) op[m] = bi[m];
}

// ---------------------------------------------------------------------------
// Kernel 2: fused projections. 64 rows/CTA, 256 threads, grid 256.
// x = feats@fc1+b  (kept in smem) ; q/k/v = x@{wq,wk,wv} -> global.
// ---------------------------------------------------------------------------
__global__ void __launch_bounds__(256) proj_kernel(
    const float* __restrict__ feats,
    const float* __restrict__ fc1_w, const float* __restrict__ fc1_b,
    const float* __restrict__ wq, const float* __restrict__ wk,
    const float* __restrict__ wv)
{
    extern __shared__ float sm2[];
    float* sW = sm2;            // 16384
    float* sA = sm2 + 16384;    // 8192  (x rows, stride 128)
    float* sF = sm2 + 24576;    // 4096  (feature rows, stride 64)
    int t = threadIdx.x;
    int g0 = blockIdx.x * 64;

    // load features (64x64) and fc1 (64x128)
    for (int o = t; o < 1024; o += 256)
        *(float4*)(sF + o*4) = *(const float4*)(feats + (size_t)g0*64 + o*4);
    for (int o = t; o < 2048; o += 256)
        *(float4*)(sW + o*4) = *(const float4*)(fc1_w + o*4);
    __syncthreads();

    gemm64<64, 64, false, true>(sF, sW, sA, fc1_b, t);
    __syncthreads();

    // q
    for (int o = t; o < 4096; o += 256)
        *(float4*)(sW + o*4) = *(const float4*)(wq + o*4);
    __syncthreads();
    gemm64<128, 128, false, false>(sA, sW, g_q + (size_t)g0*128, nullptr, t);
    __syncthreads();
    // k
    for (int o = t; o < 4096; o += 256)
        *(float4*)(sW + o*4) = *(const float4*)(wk + o*4);
    __syncthreads();
    gemm64<128, 128, false, false>(sA, sW, g_k + (size_t)g0*128, nullptr, t);
    __syncthreads();
    // v
    for (int o = t; o < 4096; o += 256)
        *(float4*)(sW + o*4) = *(const float4*)(wv + o*4);
    __syncthreads();
    gemm64<128, 128, false, false>(sA, sW, g_v + (size_t)g0*128, nullptr, t);
}

// ---------------------------------------------------------------------------
// Kernel 3: fused main. 4 nodes (64 K-rows) per CTA, 256 threads, 4096 CTAs.
// ---------------------------------------------------------------------------
__global__ void __launch_bounds__(256, 1) main_kernel(
    const float* __restrict__ xyz, const float* __restrict__ features,
    const float* __restrict__ d1_w, const float* __restrict__ d1_b,
    const float* __restrict__ d2_w, const float* __restrict__ d2_b,
    const float* __restrict__ g1_w, const float* __restrict__ g1_b,
    const float* __restrict__ g2_w, const float* __restrict__ g2_b,
    const float* __restrict__ fc2_w, const float* __restrict__ fc2_b,
    float* __restrict__ out)
{
    extern __shared__ float sm[];
    float* sW   = sm;                 // 16384
    float* sA   = sW   + 16384;       // 8192 (stride 128)
    float* sC   = sA   + 8192;        // 8192
    float* sPos = sC   + 8192;        // 8192
    float* sQ   = sPos + 8192;        // 512
    float* sRes = sQ   + 512;         // 512
    float* sD1  = sRes + 512;         // 384
    float* sD1b = sD1  + 384;         // 128
    float* sD2b = sD1b + 128;         // 128
    float* sG1b = sD2b + 128;         // 128
    float* sG2b = sG1b + 128;         // 128
    float* sRel = sG2b + 128;         // 192
    int*   sIdx = (int*)(sRel + 192); // 64

    int t = threadIdx.x;
    int g0 = blockIdx.x * 4;          // first global node of this CTA
    int bbase = (g0 >> 12) << 12;     // b * 4096

    // Phase 0: small loads
    if (t < 64) sIdx[t] = g_idx[(size_t)g0*Kn + t];
    if (t >= 64 && t < 192)
        *(float4*)(sQ + (t-64)*4) = *(const float4*)(g_q + (size_t)g0*128 + (t-64)*4);
    for (int o = t; o < 384; o += 256) sD1[o] = d1_w[o];
    if (t < 128) {
        sD1b[t] = d1_b[t]; sD2b[t] = d2_b[t];
        sG1b[t] = g1_b[t]; sG2b[t] = g2_b[t];
    }
    __syncthreads();

    // Phase 1: rel = xyz[query] - xyz[neighbor]
    if (t < 64) {
        int nn = t >> 4;
        int n  = g0 + nn;
        int j  = sIdx[t];
        const float* pq = xyz + (size_t)n * 3;
        const float* pj = xyz + (size_t)(bbase + j) * 3;
        sRel[t*3+0] = pq[0] - pj[0];
        sRel[t*3+1] = pq[1] - pj[1];
        sRel[t*3+2] = pq[2] - pj[2];
    }
    __syncthreads();

    // Phase 2: t1 = relu(rel @ d1 + d1_b) -> sA ; load d2 -> sW
    for (int o4 = t; o4 < 2048; o4 += 256) {
        int r = o4 >> 5, c = (o4 & 31) * 4;
        float rx = sRel[r*3+0], ry = sRel[r*3+1], rz = sRel[r*3+2];
        float4 w0 = *(const float4*)(sD1 + c);
        float4 w1 = *(const float4*)(sD1 + 128 + c);
        float4 w2 = *(const float4*)(sD1 + 256 + c);
        float4 bb = *(const float4*)(sD1b + c);
        float4 v;
        v.x = fmaxf(fmaf(rz, w2.x, fmaf(ry, w1.x, fmaf(rx, w0.x, bb.x))), 0.f);
        v.y = fmaxf(fmaf(rz, w2.y, fmaf(ry, w1.y, fmaf(rx, w0.y, bb.y))), 0.f);
        v.z = fmaxf(fmaf(rz, w2.z, fmaf(ry, w1.z, fmaf(rx, w0.z, bb.z))), 0.f);
        v.w = fmaxf(fmaf(rz, w2.w, fmaf(ry, w1.w, fmaf(rx, w0.w, bb.w))), 0.f);
        *(float4*)(sA + r*128 + c) = v;
    }
    for (int o = t; o < 4096; o += 256)
        *(float4*)(sW + o*4) = *(const float4*)(d2_w + o*4);
    __syncthreads();

    // Phase 3: pos = t1 @ d2 + d2_b
    gemm64<128, 128, false, true>(sA, sW, sPos, sD2b, t);
    __syncthreads();

    // Phase 4: h = q - k_gather + pos -> sA ; load g1 -> sW
    for (int o4 = t; o4 < 2048; o4 += 256) {
        int r = o4 >> 5, c = (o4 & 31) * 4;
        int nn = r >> 4;
        int j = sIdx[r];
        float4 kv = *(const float4*)(g_k + (size_t)(bbase + j)*128 + c);
        float4 qv = *(const float4*)(sQ + nn*128 + c);
        float4 pv = *(const float4*)(sPos + r*128 + c);
        float4 h;
        h.x = qv.x - kv.x + pv.x;
        h.y = qv.y - kv.y + pv.y;
        h.z = qv.z - kv.z + pv.z;
        h.w = qv.w - kv.w + pv.w;
        *(float4*)(sA + r*128 + c) = h;
    }
    for (int o = t; o < 4096; o += 256)
        *(float4*)(sW + o*4) = *(const float4*)(g1_w + o*4);
    __syncthreads();

    // Phase 5: a1 = relu(h @ g1 + g1_b)
    gemm64<128, 128, true, true>(sA, sW, sC, sG1b, t);
    __syncthreads();

    // Phase 6: load g2
    for (int o = t; o < 4096; o += 256)
        *(float4*)(sW + o*4) = *(const float4*)(g2_w + o*4);
    __syncthreads();

    // Phase 7: logits = a1 @ g2 + g2_b -> sA
    gemm64<128, 128, false, true>(sC, sW, sA, sG2b, t);
    __syncthreads();

    // Phase 8: load fc2 -> sW ; softmax over K; res accumulation; attn -> sC
    for (int o = t; o < 2048; o += 256)
        *(float4*)(sW + o*4) = *(const float4*)(fc2_w + o*4);
    for (int p = t; p < 512; p += 256) {
        int nn = p >> 7, c = p & 127;
        int r0 = nn << 4;
        float m = -3.4e38f;
#pragma unroll
        for (int k = 0; k < Kn; k++) m = fmaxf(m, sA[(r0+k)*128 + c]);
        float e[Kn];
        float ssum = 0.f;
#pragma unroll
        for (int k = 0; k < Kn; k++) {
            e[k] = __expf((sA[(r0+k)*128 + c] - m) * SCALE_F);
            ssum += e[k];
        }
        float inv = 1.f / ssum;
        float racc = 0.f;
#pragma unroll
        for (int k = 0; k < Kn; k++) {
            float a = e[k] * inv;
            sC[(r0+k)*128 + c] = a;
            int j = sIdx[r0 + k];
            float vp = g_v[(size_t)(bbase + j)*128 + c] + sPos[(r0+k)*128 + c];
            racc = fmaf(a, vp, racc);
        }
        sRes[nn*128 + c] = racc;
    }
    __syncthreads();

    // Phase 9a: dump attn (contiguous block for this CTA)
    {
        float* attn_base = out + (size_t)ATT_OFF + (size_t)g0 * (Kn * DM);
        for (int o4 = t; o4 < 2048; o4 += 256)
            *(float4*)(attn_base + o4*4) = *(const float4*)(sC + o4*4);
    }

    // Phase 9b: out = res @ fc2 + fc2_b + pre   (4 nodes x 64 = 256 outputs)
    {
        int nn = t >> 6, d = t & 63;
        float acc = fc2_b[d] + features[(size_t)(g0 + nn)*64 + d];
        const float* rr = sRes + nn*128;
#pragma unroll 8
        for (int c = 0; c < 128; c++)
            acc = fmaf(rr[c], sW[c*64 + d], acc);
        out[(size_t)(g0 + nn)*64 + d] = acc;
    }
}

// ---------------------------------------------------------------------------
extern "C" void kernel_launch(void* const* d_in, const int* in_sizes, int n_in,
                              void* d_out, int out_size) {
    const float* xyz   = (const float*)d_in[0];
    const float* feats = (const float*)d_in[1];
    const float* fc1_w = (const float*)d_in[2];
    const float* fc1_b = (const float*)d_in[3];
    const float* fc2_w = (const float*)d_in[4];
    const float* fc2_b = (const float*)d_in[5];
    const float* d1_w  = (const float*)d_in[6];
    const float* d1_b  = (const float*)d_in[7];
    const float* d2_w  = (const float*)d_in[8];
    const float* d2_b  = (const float*)d_in[9];
    const float* g1_w  = (const float*)d_in[10];
    const float* g1_b  = (const float*)d_in[11];
    const float* g2_w  = (const float*)d_in[12];
    const float* g2_b  = (const float*)d_in[13];
    const float* wq    = (const float*)d_in[14];
    const float* wk    = (const float*)d_in[15];
    const float* wv    = (const float*)d_in[16];
    float* outp = (float*)d_out;

    const int SMEM_PROJ = 28672 * 4;   // 114688 B
    const int SMEM_MAIN = 43136 * 4;   // 172544 B
    cudaFuncSetAttribute(proj_kernel, cudaFuncAttributeMaxDynamicSharedMemorySize, SMEM_PROJ);
    cudaFuncSetAttribute(main_kernel, cudaFuncAttributeMaxDynamicSharedMemorySize, SMEM_MAIN);

    knn_kernel<<<dim3(Nn/128, Bn), 128>>>(xyz);
    proj_kernel<<<NODES/64, 256, SMEM_PROJ>>>(feats, fc1_w, fc1_b, wq, wk, wv);
    main_kernel<<<NODES/4, 256, SMEM_MAIN>>>(xyz, feats,
                                             d1_w, d1_b, d2_w, d2_b,
                                             g1_w, g1_b, g2_w, g2_b,
                                             fc2_w, fc2_b, outp);
}